// round 6
// baseline (speedup 1.0000x reference)
#include <cuda_runtime.h>
#include <math.h>

#define Bsz   128
#define Tlen  256
#define NCLS  128
#define WD    512
#define UNITS 512
#define N4    2048      // 4*UNITS
#define KX    640       // NC + WD (non-recurrent input dims)
#define KTOT  1152      // KX + UNITS

typedef unsigned long long ull;

// ---------------- tiny device scratch ----------------
__device__ float g_h[2][UNITS * Bsz];   // h, unit-major [u][b], double-buffered
__device__ float g_c[UNITS * Bsz];      // c, unit-major [u][b]
__device__ float g_S[N4];               // colsum of W[640:768] (t==0 start vec)
__device__ int   g_prev[Bsz];           // prev argmax (-1 => t==0)

// packed fp32x2 FMA: d.lo += a.lo*b.lo ; d.hi += a.hi*b.hi  (IEEE per lane)
__device__ __forceinline__ void ffma2(ull& d, ull a, ull b) {
    asm("fma.rn.f32x2 %0, %1, %2, %0;" : "+l"(d) : "l"(a), "l"(b));
}

// ---------------- init: zero state, prev = -1 ----------------
__global__ void k_init() {
    int i = blockIdx.x * blockDim.x + threadIdx.x;   // 65536 threads
    g_h[0][i] = 0.0f;
    g_c[i]    = 0.0f;
    if (i < Bsz) g_prev[i] = -1;
}

// ---------------- S[j] = sum_i W[640+i][j] ----------------
__global__ void k_colsum(const float* __restrict__ W) {
    int j = blockIdx.x * blockDim.x + threadIdx.x;   // 2048 threads
    float s = 0.0f;
    #pragma unroll
    for (int i = 0; i < NCLS; i++)
        s += W[(size_t)(KX + i) * N4 + j];
    g_S[j] = s;
}

// ---------------- fused per-step kernel -----------------------------------------
// z[b, col] = sum_{k<640} x_t[b,k] W[k,col] + sum_k h[k,b] U[k,col]
//           + bias[col] + W[640+prev[b], col]        (or 1e-5*S at t==0)
// then gates (Keras i,f,g,o) -> new c, h.
// Grid: 128 blocks x 128 threads. Block owns 4 units x 4 gates = 16 cols, all 128 b.
__global__ __launch_bounds__(128) void k_step(int t,
                                              const float* __restrict__ xc,
                                              const float* __restrict__ xw,
                                              const float* __restrict__ W,
                                              const float* __restrict__ U,
                                              const float* __restrict__ bias) {
    __shared__ float vs[64][132];   // [k][b] input chunk (row = 528B, 16B aligned)
    __shared__ ull   ws2[64][16];   // [k][c] weight, duplicated (w,w) for fp32x2

    const int tid    = threadIdx.x;
    const int bq     = tid & 63;
    const int cg     = tid >> 6;          // 0..1
    const int u_base = blockIdx.x * 4;

    const float* __restrict__ hin = g_h[t & 1];
    float* hout = g_h[(t + 1) & 1];

    ull acc[8];                           // acc[j] <-> c = cg*8 + j ; lanes = (b even, b odd)
    #pragma unroll
    for (int j = 0; j < 8; j++) acc[j] = 0ull;

    for (int ch = 0; ch < KTOT / 64; ch++) {    // 18 chunks of 64 k
        const int kk = ch * 64;
        __syncthreads();

        // ---- stage input chunk vs[k][b] ----
        if (kk < KX) {
            // x part: thread == batch row; 64 contiguous floats from x_char/x_word
            const float* src = (kk < NCLS)
                ? xc + ((size_t)tid * Tlen + t) * NCLS + kk
                : xw + ((size_t)tid * Tlen + t) * WD + (kk - NCLS);
            #pragma unroll
            for (int q = 0; q < 16; q++) {
                float4 v = *(const float4*)(src + q * 4);
                vs[q * 4 + 0][tid] = v.x;
                vs[q * 4 + 1][tid] = v.y;
                vs[q * 4 + 2][tid] = v.z;
                vs[q * 4 + 3][tid] = v.w;
            }
        } else {
            // h part: unit-major rows contiguous over b -> coalesced float4 copy
            #pragma unroll
            for (int i = 0; i < 16; i++) {
                int vi = tid + 128 * i;           // 0..2047 float4s
                int k  = vi >> 5;                 // 0..63
                int b4 = vi & 31;                 // 0..31
                float4 v = *(const float4*)&hin[(size_t)(kk - KX + k) * Bsz + b4 * 4];
                *(float4*)&vs[k][b4 * 4] = v;
            }
        }

        // ---- stage weights ws2[k][c] = (w,w), c = uo*4+g ----
        #pragma unroll
        for (int i = 0; i < 8; i++) {
            int idx = tid + 128 * i;              // 0..1023
            int k   = idx >> 4;                   // 0..63
            int c   = idx & 15;
            int col = (c & 3) * 512 + u_base + (c >> 2);
            int kg  = kk + k;
            float w = (kg < KX) ? __ldg(&W[(size_t)kg * N4 + col])
                                : __ldg(&U[(size_t)(kg - KX) * N4 + col]);
            ull p;
            asm("mov.b64 %0, {%1, %2};" : "=l"(p) : "f"(w), "f"(w));
            ws2[k][c] = p;
        }
        __syncthreads();

        // ---- FFMA2 inner loop: 8 cols x 2 b per thread ----
        #pragma unroll 8
        for (int k = 0; k < 64; k++) {
            ull hv = *(const ull*)&vs[k][2 * bq];           // (v[b0], v[b1])
            const ull* wr = &ws2[k][cg * 8];
            ulonglong2 w0 = *(const ulonglong2*)&wr[0];
            ulonglong2 w1 = *(const ulonglong2*)&wr[2];
            ulonglong2 w2 = *(const ulonglong2*)&wr[4];
            ulonglong2 w3 = *(const ulonglong2*)&wr[6];
            ffma2(acc[0], hv, w0.x);  ffma2(acc[1], hv, w0.y);
            ffma2(acc[2], hv, w1.x);  ffma2(acc[3], hv, w1.y);
            ffma2(acc[4], hv, w2.x);  ffma2(acc[5], hv, w2.y);
            ffma2(acc[6], hv, w3.x);  ffma2(acc[7], hv, w3.y);
        }
    }

    // ---- epilogue: unpack, add bias + prev-word row, gates, write c/h ----
    float zlo[8], zhi[8];
    #pragma unroll
    for (int j = 0; j < 8; j++)
        asm("mov.b64 {%0, %1}, %2;" : "=f"(zlo[j]), "=f"(zhi[j]) : "l"(acc[j]));

    #pragma unroll
    for (int uu = 0; uu < 2; uu++) {
        const int u = u_base + 2 * cg + uu;
        #pragma unroll
        for (int r = 0; r < 2; r++) {
            const int b  = 2 * bq + r;
            const int pi = g_prev[b];
            float z[4];
            #pragma unroll
            for (int g = 0; g < 4; g++) {
                const int col = g * 512 + u;
                float zv  = r ? zhi[uu * 4 + g] : zlo[uu * 4 + g];
                float add = (pi < 0) ? 1e-5f * g_S[col]
                                     : __ldg(&W[(size_t)(KX + pi) * N4 + col]);
                z[g] = zv + __ldg(&bias[col]) + add;
            }
            float i_ = 1.0f / (1.0f + expf(-z[0]));
            float f_ = 1.0f / (1.0f + expf(-z[1]));
            float gv = tanhf(z[2]);
            float o_ = 1.0f / (1.0f + expf(-z[3]));
            float cn = f_ * g_c[(size_t)u * Bsz + b] + i_ * gv;
            float hn = o_ * tanhf(cn);
            g_c[(size_t)u * Bsz + b]  = cn;
            hout[(size_t)u * Bsz + b] = hn;
        }
    }
}

// ---------------- per-step: logits = h@Ws + bs ; argmax ; emit index ------------
// OUTPUT IS WRITTEN AS float32 (see theory: __output__ dtype is f32; int bits
// read as denormals explain the exact rel_err = 1.0 across all prior rounds).
__global__ __launch_bounds__(128) void k_out(int t,
                                             const float* __restrict__ Ws,
                                             const float* __restrict__ bsv,
                                             float* __restrict__ out) {
    __shared__ float hs[UNITS];
    __shared__ float rv[4];
    __shared__ int   ri[4];

    const int b = blockIdx.x;
    const int j = threadIdx.x;            // 0..127, one logit per thread
    const float* __restrict__ hT = g_h[(t + 1) & 1];

    #pragma unroll
    for (int i = 0; i < 4; i++) {
        int k = j * 4 + i;
        hs[k] = hT[(size_t)k * Bsz + b];
    }
    __syncthreads();

    float acc = __ldg(&bsv[j]);
    #pragma unroll 8
    for (int k = 0; k < UNITS; k++)
        acc += hs[k] * __ldg(&Ws[k * NCLS + j]);

    // argmax, lowest index wins ties (matches jnp.argmax; softmax is monotone)
    float v  = acc;
    int   bi = j;
    #pragma unroll
    for (int off = 16; off > 0; off >>= 1) {
        float ov = __shfl_down_sync(0xffffffffu, v, off);
        int   oi = __shfl_down_sync(0xffffffffu, bi, off);
        if (ov > v || (ov == v && oi < bi)) { v = ov; bi = oi; }
    }
    if ((j & 31) == 0) { rv[j >> 5] = v; ri[j >> 5] = bi; }
    __syncthreads();
    if (j == 0) {
        #pragma unroll
        for (int w = 1; w < 4; w++)
            if (rv[w] > v || (rv[w] == v && ri[w] < bi)) { v = rv[w]; bi = ri[w]; }
        out[b * Tlen + t] = (float)bi;    // float32 output
        g_prev[b] = bi;
    }
}

// ---------------- launch ----------------
// Bind by element count (all 7 are pairwise distinct); fall back to the
// reference positional order (x_char, x_word, W, U, b, Ws, bs) if needed.
extern "C" void kernel_launch(void* const* d_in, const int* in_sizes, int n_in,
                              void* d_out, int out_size) {
    (void)out_size;
    const float *xc = 0, *xw = 0, *W = 0, *U = 0, *bias = 0, *Ws = 0, *bs = 0;
    for (int i = 0; i < n_in; i++) {
        switch (in_sizes[i]) {
            case 4194304:  xc   = (const float*)d_in[i]; break;  // 128*256*128
            case 16777216: xw   = (const float*)d_in[i]; break;  // 128*256*512
            case 1572864:  W    = (const float*)d_in[i]; break;  // 768*2048
            case 1048576:  U    = (const float*)d_in[i]; break;  // 512*2048
            case 2048:     bias = (const float*)d_in[i]; break;
            case 65536:    Ws   = (const float*)d_in[i]; break;  // 512*128
            case 128:      bs   = (const float*)d_in[i]; break;
            default: break;
        }
    }
    if ((!xc || !xw || !W || !U || !bias || !Ws || !bs) && n_in >= 7) {
        xc   = (const float*)d_in[0];
        xw   = (const float*)d_in[1];
        W    = (const float*)d_in[2];
        U    = (const float*)d_in[3];
        bias = (const float*)d_in[4];
        Ws   = (const float*)d_in[5];
        bs   = (const float*)d_in[6];
    }
    float* out = (float*)d_out;           // [B,T] as float32

    k_init<<<256, 256>>>();
    k_colsum<<<8, 256>>>(W);

    for (int t = 0; t < Tlen; t++) {
        k_step<<<128, 128>>>(t, xc, xw, W, U, bias);
        k_out<<<Bsz, 128>>>(t, Ws, bs, out);
    }
}

// round 7
// speedup vs baseline: 1.5604x; 1.5604x over previous
#include <cuda_runtime.h>
#include <math.h>
#include <stdint.h>

#define Bsz   128
#define Tlen  256
#define NCLS  128
#define WD    512
#define UNITS 512
#define N4    2048      // 4*UNITS
#define KX    640       // NC + WD
#define KTOT  1152      // KX + UNITS
#define NCH   18        // KTOT / 64

typedef unsigned long long ull;

// ---------------- device scratch ----------------
__device__ float g_h [2][UNITS * Bsz];          // [u][b], double-buffered
__device__ float g_hT[2][Bsz * UNITS];          // [b][u], for k_out coalesced stage
__device__ float g_c [UNITS * Bsz];             // [u][b]
__device__ int   g_prev[Bsz];                   // prev argmax (-1 => t==0)
__device__ ull   g_Wp[(size_t)128 * KTOT * 16]; // packed (w,w): [block][k][c]  (~19MB)
__device__ float g_Wfb[(size_t)NCLS * N4];      // feedback rows, block-local col order
__device__ float g_biasP[N4];                   // bias, block-local col order
__device__ float g_SP[N4];                      // 1e-5 start-vec colsum, block-local order
__device__ float g_xT[(size_t)Tlen * KX * Bsz]; // x transposed: [t][k][b]  (~84MB)

__device__ __forceinline__ void ffma2(ull& d, ull a, ull b) {
    asm("fma.rn.f32x2 %0, %1, %2, %0;" : "+l"(d) : "l"(a), "l"(b));
}
__device__ __forceinline__ void cpa16(uint32_t dst, const void* src) {
    asm volatile("cp.async.cg.shared.global [%0], [%1], 16;" :: "r"(dst), "l"(src) : "memory");
}
__device__ __forceinline__ void cpa_commit() {
    asm volatile("cp.async.commit_group;" ::: "memory");
}

// col (0..2047) -> (block, c) in packed order: col = g*512 + block*4 + uu ; c = uu*4+g
__device__ __forceinline__ void col2bc(int col, int& blk, int& c) {
    int g  = col >> 9;
    int u  = col & 511;
    blk    = u >> 2;
    c      = (u & 3) * 4 + g;
}

// ---------------- init ----------------
__global__ void k_init() {
    int i = blockIdx.x * blockDim.x + threadIdx.x;   // 65536
    g_h [0][i] = 0.0f;
    g_hT[0][i] = 0.0f;
    g_c[i]     = 0.0f;
    if (i < Bsz) g_prev[i] = -1;
}

// ---------------- one-time: pack weights (coalesced reads over col) ----------------
__global__ void k_packW(const float* __restrict__ W, const float* __restrict__ U) {
    int idx = blockIdx.x * blockDim.x + threadIdx.x;   // KTOT*2048 threads
    int k   = idx >> 11;
    int col = idx & 2047;
    if (k >= KTOT) return;
    float w = (k < KX) ? W[(size_t)k * N4 + col] : U[(size_t)(k - KX) * N4 + col];
    int blk, c; col2bc(col, blk, c);
    ull p;
    asm("mov.b64 %0, {%1, %2};" : "=l"(p) : "f"(w), "f"(w));
    g_Wp[((size_t)blk * KTOT + k) * 16 + c] = p;
}

// ---------------- one-time: bias / start-vec / feedback rows in packed order --------
__global__ void k_packMisc(const float* __restrict__ W, const float* __restrict__ bias) {
    int idx = blockIdx.x * blockDim.x + threadIdx.x;   // 128*2048 threads
    int pi  = idx >> 11;
    int col = idx & 2047;
    int blk, c; col2bc(col, blk, c);
    int dst = blk * 16 + c;
    g_Wfb[(size_t)pi * N4 + dst] = W[(size_t)(KX + pi) * N4 + col];
    if (pi == 0) {
        g_biasP[dst] = bias[col];
        float s = 0.0f;
        #pragma unroll
        for (int i = 0; i < NCLS; i++) s += W[(size_t)(KX + i) * N4 + col];
        g_SP[dst] = s;
    }
}

// ---------------- one-time: transpose x -> g_xT[t][k][b] ----------------
__global__ void k_xT(const float* __restrict__ xc, const float* __restrict__ xw) {
    __shared__ float tile[32][33];
    int t  = blockIdx.x;
    int kt = blockIdx.y;       // 0..19
    int bt = blockIdx.z;       // 0..3
    int tx = threadIdx.x;      // 0..31
    int ty = threadIdx.y;      // 0..7
    #pragma unroll
    for (int i = 0; i < 4; i++) {
        int b = bt * 32 + ty + 8 * i;
        int k = kt * 32 + tx;
        float v = (k < NCLS) ? xc[((size_t)b * Tlen + t) * NCLS + k]
                             : xw[((size_t)b * Tlen + t) * WD + (k - NCLS)];
        tile[ty + 8 * i][tx] = v;
    }
    __syncthreads();
    #pragma unroll
    for (int i = 0; i < 4; i++) {
        int k = kt * 32 + ty + 8 * i;
        int b = bt * 32 + tx;
        g_xT[((size_t)t * KX + k) * Bsz + b] = tile[tx][ty + 8 * i];
    }
}

// ---------------- per-step fused gate kernel (cp.async 2-stage pipeline) ----------
// grid 128 (unit-groups), block 128.  smem: vs[2][64][132] f32 + ws[2][64][16] ull
#define VS_ELE   (64 * 132)
#define WS_ELE   (64 * 16)
#define SMEM_STEP (2 * VS_ELE * 4 + 2 * WS_ELE * 8)

__global__ __launch_bounds__(128) void k_step(int t) {
    extern __shared__ char sm[];
    float* vsb = (float*)sm;                       // [2][64][132]
    ull*   wsb = (ull*)(sm + 2 * VS_ELE * 4);      // [2][64][16]

    const int tid = threadIdx.x;
    const int bq  = tid & 63;
    const int cg  = tid >> 6;                      // 0..1
    const int blk = blockIdx.x;

    const float* __restrict__ hin = g_h[t & 1];
    float* hout  = g_h [(t + 1) & 1];
    float* houtT = g_hT[(t + 1) & 1];
    const ull* __restrict__ wsrc = g_Wp + (size_t)blk * KTOT * 16;

    const uint32_t vs_s = (uint32_t)__cvta_generic_to_shared(vsb);
    const uint32_t ws_s = (uint32_t)__cvta_generic_to_shared(wsb);

    // issue staging for chunk ch into buffer buf
    auto issue = [&](int ch, int buf) {
        const float* src = (ch < 10)
            ? g_xT + ((size_t)t * KX + ch * 64) * Bsz
            : hin  + (size_t)(ch - 10) * 64 * Bsz;
        uint32_t vdst = vs_s + buf * VS_ELE * 4;
        #pragma unroll
        for (int i = 0; i < 16; i++) {
            int vi = tid + 128 * i;                // 0..2047
            int k  = vi >> 5;
            int b4 = vi & 31;
            cpa16(vdst + (k * 132 + b4 * 4) * 4, src + k * Bsz + b4 * 4);
        }
        const char* wsrcb = (const char*)(wsrc + ch * 64 * 16);
        uint32_t wdst = ws_s + buf * WS_ELE * 8 + tid * 64;
        #pragma unroll
        for (int q = 0; q < 4; q++)
            cpa16(wdst + q * 16, wsrcb + tid * 64 + q * 16);
        cpa_commit();
    };

    ull acc[8];
    #pragma unroll
    for (int j = 0; j < 8; j++) acc[j] = 0ull;

    issue(0, 0);
    issue(1, 1);

    for (int ch = 0; ch < NCH; ch++) {
        if (ch < NCH - 2) asm volatile("cp.async.wait_group 1;" ::: "memory");
        else              asm volatile("cp.async.wait_group 0;" ::: "memory");
        __syncthreads();

        const float* vrow = vsb + (ch & 1) * VS_ELE;
        const ull*   wrow = wsb + (ch & 1) * WS_ELE;

        #pragma unroll 8
        for (int k = 0; k < 64; k++) {
            ull hv = *(const ull*)(vrow + k * 132 + 2 * bq);
            const ull* wr = wrow + k * 16 + cg * 8;
            ulonglong2 w0 = *(const ulonglong2*)&wr[0];
            ulonglong2 w1 = *(const ulonglong2*)&wr[2];
            ulonglong2 w2 = *(const ulonglong2*)&wr[4];
            ulonglong2 w3 = *(const ulonglong2*)&wr[6];
            ffma2(acc[0], hv, w0.x);  ffma2(acc[1], hv, w0.y);
            ffma2(acc[2], hv, w1.x);  ffma2(acc[3], hv, w1.y);
            ffma2(acc[4], hv, w2.x);  ffma2(acc[5], hv, w2.y);
            ffma2(acc[6], hv, w3.x);  ffma2(acc[7], hv, w3.y);
        }
        __syncthreads();
        if (ch + 2 < NCH) issue(ch + 2, ch & 1);
    }

    // epilogue
    float zlo[8], zhi[8];
    #pragma unroll
    for (int j = 0; j < 8; j++)
        asm("mov.b64 {%0, %1}, %2;" : "=f"(zlo[j]), "=f"(zhi[j]) : "l"(acc[j]));

    #pragma unroll
    for (int uu = 0; uu < 2; uu++) {
        const int u = blk * 4 + 2 * cg + uu;
        #pragma unroll
        for (int r = 0; r < 2; r++) {
            const int b  = 2 * bq + r;
            const int pi = g_prev[b];
            float z[4];
            #pragma unroll
            for (int g = 0; g < 4; g++) {
                const int c   = cg * 8 + uu * 4 + g;
                const int dst = blk * 16 + c;
                float zv  = r ? zhi[uu * 4 + g] : zlo[uu * 4 + g];
                float add = (pi < 0) ? 1e-5f * g_SP[dst]
                                     : __ldg(&g_Wfb[(size_t)pi * N4 + dst]);
                z[g] = zv + g_biasP[dst] + add;
            }
            float i_ = 1.0f / (1.0f + expf(-z[0]));
            float f_ = 1.0f / (1.0f + expf(-z[1]));
            float gv = tanhf(z[2]);
            float o_ = 1.0f / (1.0f + expf(-z[3]));
            float cn = f_ * g_c[(size_t)u * Bsz + b] + i_ * gv;
            float hn = o_ * tanhf(cn);
            g_c[(size_t)u * Bsz + b]   = cn;
            hout [(size_t)u * Bsz + b] = hn;
            houtT[(size_t)b * UNITS + u] = hn;
        }
    }
}

// ---------------- per-step: logits + argmax, 4 batches/block, split-K=4 ------------
__global__ __launch_bounds__(512) void k_out(int t,
                                             const float* __restrict__ Ws,
                                             const float* __restrict__ bsv,
                                             float* __restrict__ out) {
    __shared__ float hs[4][UNITS];        // 8KB
    __shared__ float red[3][4][NCLS];     // 6KB
    __shared__ float candV[4][4];
    __shared__ int   candI[4][4];

    const int tid = threadIdx.x;
    const int b0  = blockIdx.x * 4;
    const float* __restrict__ hT = g_hT[(t + 1) & 1];

    // stage h for 4 batches: 512 float4s, one per thread, coalesced
    {
        int r   = tid >> 7;               // 0..3
        int off = (tid & 127) * 4;
        *(float4*)&hs[r][off] = *(const float4*)&hT[(size_t)(b0 + r) * UNITS + off];
    }
    __syncthreads();

    const int j = tid & 127;
    const int s = tid >> 7;               // split-K id 0..3
    const int k0 = s * 128;

    float a0 = 0.f, a1 = 0.f, a2 = 0.f, a3 = 0.f;   // per-batch accumulators
    #pragma unroll 4
    for (int k = 0; k < 128; k++) {
        float w = __ldg(&Ws[(size_t)(k0 + k) * NCLS + j]);
        a0 += hs[0][k0 + k] * w;
        a1 += hs[1][k0 + k] * w;
        a2 += hs[2][k0 + k] * w;
        a3 += hs[3][k0 + k] * w;
    }
    if (s > 0) {
        red[s - 1][0][j] = a0;  red[s - 1][1][j] = a1;
        red[s - 1][2][j] = a2;  red[s - 1][3][j] = a3;
    }
    __syncthreads();

    if (s == 0) {
        float bj = __ldg(&bsv[j]);
        float tot[4] = {
            a0 + red[0][0][j] + red[1][0][j] + red[2][0][j] + bj,
            a1 + red[0][1][j] + red[1][1][j] + red[2][1][j] + bj,
            a2 + red[0][2][j] + red[1][2][j] + red[2][2][j] + bj,
            a3 + red[0][3][j] + red[1][3][j] + red[2][3][j] + bj
        };
        int warp = j >> 5;
        #pragma unroll
        for (int r = 0; r < 4; r++) {
            float v  = tot[r];
            int   bi = j;
            #pragma unroll
            for (int off = 16; off > 0; off >>= 1) {
                float ov = __shfl_down_sync(0xffffffffu, v, off);
                int   oi = __shfl_down_sync(0xffffffffu, bi, off);
                if (ov > v || (ov == v && oi < bi)) { v = ov; bi = oi; }
            }
            if ((j & 31) == 0) { candV[r][warp] = v; candI[r][warp] = bi; }
        }
    }
    __syncthreads();
    if (tid < 4) {
        int r = tid;
        float v  = candV[r][0];
        int   bi = candI[r][0];
        #pragma unroll
        for (int w = 1; w < 4; w++)
            if (candV[r][w] > v) { v = candV[r][w]; bi = candI[r][w]; }
        out[(size_t)(b0 + r) * Tlen + t] = (float)bi;
        g_prev[b0 + r] = bi;
    }
}

// ---------------- launch ----------------
extern "C" void kernel_launch(void* const* d_in, const int* in_sizes, int n_in,
                              void* d_out, int out_size) {
    (void)out_size;
    const float *xc = 0, *xw = 0, *W = 0, *U = 0, *bias = 0, *Ws = 0, *bs = 0;
    for (int i = 0; i < n_in; i++) {
        switch (in_sizes[i]) {
            case 4194304:  xc   = (const float*)d_in[i]; break;
            case 16777216: xw   = (const float*)d_in[i]; break;
            case 1572864:  W    = (const float*)d_in[i]; break;
            case 1048576:  U    = (const float*)d_in[i]; break;
            case 2048:     bias = (const float*)d_in[i]; break;
            case 65536:    Ws   = (const float*)d_in[i]; break;
            case 128:      bs   = (const float*)d_in[i]; break;
            default: break;
        }
    }
    if ((!xc || !xw || !W || !U || !bias || !Ws || !bs) && n_in >= 7) {
        xc = (const float*)d_in[0]; xw = (const float*)d_in[1];
        W  = (const float*)d_in[2]; U  = (const float*)d_in[3];
        bias = (const float*)d_in[4]; Ws = (const float*)d_in[5];
        bs = (const float*)d_in[6];
    }
    float* out = (float*)d_out;

    cudaFuncSetAttribute(k_step, cudaFuncAttributeMaxDynamicSharedMemorySize, SMEM_STEP);

    k_init<<<256, 256>>>();
    k_packW<<<(KTOT * 2048) / 256, 256>>>(W, U);
    k_packMisc<<<(128 * 2048) / 256, 256>>>(W, bias);
    {
        dim3 g(Tlen, KX / 32, Bsz / 32);
        dim3 b(32, 8);
        k_xT<<<g, b>>>(xc, xw);
    }

    for (int t = 0; t < Tlen; t++) {
        k_step<<<128, 128, SMEM_STEP>>>(t);
        k_out<<<Bsz / 4, 512>>>(t, Ws, bs, out);
    }
}

// round 8
// speedup vs baseline: 1.7002x; 1.0896x over previous
#include <cuda_runtime.h>
#include <math.h>
#include <stdint.h>

#define Bsz   128
#define Tlen  256
#define NCLS  128
#define WD    512
#define UNITS 512
#define N4    2048      // 4*UNITS
#define KX    640       // NC + WD
#define KTOT  1152      // KX + UNITS
#define NCH   18        // KTOT / 64
#define NBLK  128       // persistent grid size (all co-resident on 148 SMs)

typedef unsigned long long ull;

// ---------------- device scratch ----------------
__device__ float g_h [2][UNITS * Bsz];          // [u][b], double-buffered
__device__ float g_hT[Bsz * UNITS];             // [b][u], for phase-2 staging
__device__ float g_c [UNITS * Bsz];             // [u][b]
__device__ int   g_prev[Bsz];                   // prev argmax (-1 => t==0)
__device__ ull   g_Wp[(size_t)128 * KTOT * 16]; // packed (w,w): [block][k][c]
__device__ float g_Wfb[(size_t)NCLS * N4];      // feedback rows, packed col order
__device__ float g_biasP[N4];                   // bias, packed col order
__device__ float g_SP[N4];                      // start-vec colsum, packed order
__device__ float g_xT[(size_t)Tlen * KX * Bsz]; // x transposed: [t][k][b]
__device__ unsigned          g_bar_count;       // grid barrier state
__device__ volatile unsigned g_bar_gen;

__device__ __forceinline__ void ffma2(ull& d, ull a, ull b) {
    asm("fma.rn.f32x2 %0, %1, %2, %0;" : "+l"(d) : "l"(a), "l"(b));
}
__device__ __forceinline__ void cpa16(uint32_t dst, const void* src) {
    asm volatile("cp.async.cg.shared.global [%0], [%1], 16;" :: "r"(dst), "l"(src) : "memory");
}
__device__ __forceinline__ void cpa_commit() {
    asm volatile("cp.async.commit_group;" ::: "memory");
}

// col (0..2047) -> (block, c): col = g*512 + blk*4 + uu ; c = uu*4 + g
__device__ __forceinline__ void col2bc(int col, int& blk, int& c) {
    int g = col >> 9;
    int u = col & 511;
    blk   = u >> 2;
    c     = (u & 3) * 4 + g;
}

// sense-reversing grid barrier (all NBLK blocks resident by construction)
__device__ __forceinline__ void grid_sync() {
    __syncthreads();
    if (threadIdx.x == 0) {
        __threadfence();
        unsigned gen = g_bar_gen;
        if (atomicAdd(&g_bar_count, 1u) == NBLK - 1) {
            g_bar_count = 0;
            __threadfence();
            g_bar_gen = gen + 1;
        } else {
            while (g_bar_gen == gen) __nanosleep(32);
        }
        __threadfence();
    }
    __syncthreads();
}

// ---------------- init ----------------
__global__ void k_init() {
    int i = blockIdx.x * blockDim.x + threadIdx.x;   // 65536
    g_h[0][i] = 0.0f;
    g_c[i]    = 0.0f;
    if (i < Bsz) g_prev[i] = -1;
    if (i == 0) { g_bar_count = 0; g_bar_gen = 0; }
}

// ---------------- one-time: pack weights ----------------
__global__ void k_packW(const float* __restrict__ W, const float* __restrict__ U) {
    int idx = blockIdx.x * blockDim.x + threadIdx.x;   // KTOT*2048
    int k   = idx >> 11;
    int col = idx & 2047;
    if (k >= KTOT) return;
    float w = (k < KX) ? W[(size_t)k * N4 + col] : U[(size_t)(k - KX) * N4 + col];
    int blk, c; col2bc(col, blk, c);
    ull p;
    asm("mov.b64 %0, {%1, %2};" : "=l"(p) : "f"(w), "f"(w));
    g_Wp[((size_t)blk * KTOT + k) * 16 + c] = p;
}

// ---------------- one-time: bias / start-vec / feedback rows ----------------
__global__ void k_packMisc(const float* __restrict__ W, const float* __restrict__ bias) {
    int idx = blockIdx.x * blockDim.x + threadIdx.x;   // 128*2048
    int pi  = idx >> 11;
    int col = idx & 2047;
    int blk, c; col2bc(col, blk, c);
    int dst = blk * 16 + c;
    g_Wfb[(size_t)pi * N4 + dst] = W[(size_t)(KX + pi) * N4 + col];
    if (pi == 0) {
        g_biasP[dst] = bias[col];
        float s = 0.0f;
        #pragma unroll
        for (int i = 0; i < NCLS; i++) s += W[(size_t)(KX + i) * N4 + col];
        g_SP[dst] = s;
    }
}

// ---------------- one-time: transpose x -> g_xT[t][k][b] ----------------
__global__ void k_xT(const float* __restrict__ xc, const float* __restrict__ xw) {
    __shared__ float tile[32][33];
    int t  = blockIdx.x;
    int kt = blockIdx.y;
    int bt = blockIdx.z;
    int tx = threadIdx.x;
    int ty = threadIdx.y;
    #pragma unroll
    for (int i = 0; i < 4; i++) {
        int b = bt * 32 + ty + 8 * i;
        int k = kt * 32 + tx;
        float v = (k < NCLS) ? xc[((size_t)b * Tlen + t) * NCLS + k]
                             : xw[((size_t)b * Tlen + t) * WD + (k - NCLS)];
        tile[ty + 8 * i][tx] = v;
    }
    __syncthreads();
    #pragma unroll
    for (int i = 0; i < 4; i++) {
        int k = kt * 32 + ty + 8 * i;
        int b = bt * 32 + tx;
        g_xT[((size_t)t * KX + k) * Bsz + b] = tile[tx][ty + 8 * i];
    }
}

// ---------------- persistent scan kernel: all 256 steps in one launch ------------
#define VS_ELE (64 * 132)
#define WS_ELE (64 * 16)
#define DSMEM  (2 * VS_ELE * 4 + 2 * WS_ELE * 8)   // 83968 B

__global__ __launch_bounds__(256) void k_scan(const float* __restrict__ Ws,
                                              const float* __restrict__ bsv,
                                              float* __restrict__ out) {
    extern __shared__ char sm[];
    float* vsb = (float*)sm;                       // [2][64][132]
    ull*   wsb = (ull*)(sm + 2 * VS_ELE * 4);      // [2][64][16]
    __shared__ float hs[UNITS];
    __shared__ float red[NCLS];
    __shared__ float candV[4];
    __shared__ int   candI[4];

    const int tid = threadIdx.x;
    const int bq  = tid & 63;                      // batch pair id
    const int cq  = tid >> 6;                      // local unit 0..3 (owns 4 gates)
    const int blk = blockIdx.x;
    const ull* __restrict__ wsrc = g_Wp + (size_t)blk * KTOT * 16;
    const uint32_t vs_s = (uint32_t)__cvta_generic_to_shared(vsb);
    const uint32_t ws_s = (uint32_t)__cvta_generic_to_shared(wsb);

    for (int t = 0; t < Tlen; t++) {
        const float* __restrict__ hin = g_h[t & 1];
        float* hout = g_h[(t + 1) & 1];

        // -------- phase 1: z = x@W + h@U (K=1152) for 16 cols, all 128 b --------
        auto issue = [&](int ch, int buf) {
            const float* src = (ch < 10)
                ? g_xT + ((size_t)t * KX + ch * 64) * Bsz
                : hin  + (size_t)(ch - 10) * 64 * Bsz;
            uint32_t vdst = vs_s + buf * VS_ELE * 4;
            #pragma unroll
            for (int i = 0; i < 8; i++) {
                int vi = tid + 256 * i;            // 0..2047 float4s
                int k  = vi >> 5;
                int b4 = vi & 31;
                cpa16(vdst + (k * 132 + b4 * 4) * 4, src + k * Bsz + b4 * 4);
            }
            const char* wsrcb = (const char*)(wsrc + ch * 64 * 16);
            uint32_t wdst = ws_s + buf * WS_ELE * 8 + tid * 32;
            cpa16(wdst,      wsrcb + tid * 32);
            cpa16(wdst + 16, wsrcb + tid * 32 + 16);
            cpa_commit();
        };

        ull acc[4] = {0ull, 0ull, 0ull, 0ull};     // 4 gates of unit cq, 2 b lanes
        issue(0, 0);
        issue(1, 1);

        for (int ch = 0; ch < NCH; ch++) {
            if (ch < NCH - 2) asm volatile("cp.async.wait_group 1;" ::: "memory");
            else              asm volatile("cp.async.wait_group 0;" ::: "memory");
            __syncthreads();

            const float* vrow = vsb + (ch & 1) * VS_ELE;
            const ull*   wrow = wsb + (ch & 1) * WS_ELE;

            #pragma unroll 8
            for (int k = 0; k < 64; k++) {
                ull hv = *(const ull*)(vrow + k * 132 + 2 * bq);
                const ull* wr = wrow + k * 16 + cq * 4;
                ulonglong2 wA = *(const ulonglong2*)&wr[0];
                ulonglong2 wB = *(const ulonglong2*)&wr[2];
                ffma2(acc[0], hv, wA.x);  ffma2(acc[1], hv, wA.y);
                ffma2(acc[2], hv, wB.x);  ffma2(acc[3], hv, wB.y);
            }
            __syncthreads();
            if (ch + 2 < NCH) issue(ch + 2, ch & 1);
        }

        // epilogue: gates (Keras i,f,g,o) -> new c, h
        const int u    = blk * 4 + cq;
        const int dstb = blk * 16 + cq * 4;
        float zl[4], zh[4];
        #pragma unroll
        for (int g = 0; g < 4; g++)
            asm("mov.b64 {%0, %1}, %2;" : "=f"(zl[g]), "=f"(zh[g]) : "l"(acc[g]));

        #pragma unroll
        for (int r = 0; r < 2; r++) {
            const int b  = 2 * bq + r;
            const int pi = g_prev[b];
            float z[4];
            #pragma unroll
            for (int g = 0; g < 4; g++) {
                float add = (pi < 0) ? 1e-5f * g_SP[dstb + g]
                                     : __ldg(&g_Wfb[(size_t)pi * N4 + dstb + g]);
                z[g] = (r ? zh[g] : zl[g]) + g_biasP[dstb + g] + add;
            }
            float i_ = 1.0f / (1.0f + expf(-z[0]));
            float f_ = 1.0f / (1.0f + expf(-z[1]));
            float gv = tanhf(z[2]);
            float o_ = 1.0f / (1.0f + expf(-z[3]));
            float cn = f_ * g_c[(size_t)u * Bsz + b] + i_ * gv;
            float hn = o_ * tanhf(cn);
            g_c[(size_t)u * Bsz + b]     = cn;
            hout[(size_t)u * Bsz + b]    = hn;
            g_hT[(size_t)b * UNITS + u]  = hn;
        }

        grid_sync();   // h(t+1) complete everywhere

        // -------- phase 2: logits + argmax for batch b = blk --------
        {
            const int b = blk;
            hs[tid]       = g_hT[(size_t)b * UNITS + tid];
            hs[tid + 256] = g_hT[(size_t)b * UNITS + tid + 256];
            __syncthreads();

            const int j = tid & 127;
            const int s = tid >> 7;                // split-K 2-way
            float a = 0.0f;
            const float* wp = Ws + (size_t)s * 256 * NCLS + j;
            #pragma unroll 8
            for (int k = 0; k < 256; k++)
                a += hs[s * 256 + k] * __ldg(wp + k * NCLS);
            if (s) red[j] = a;
            __syncthreads();

            if (!s) {
                float v  = a + red[j] + __ldg(&bsv[j]);
                int   bi = j;
                #pragma unroll
                for (int off = 16; off > 0; off >>= 1) {
                    float ov = __shfl_down_sync(0xffffffffu, v, off);
                    int   oi = __shfl_down_sync(0xffffffffu, bi, off);
                    if (ov > v || (ov == v && oi < bi)) { v = ov; bi = oi; }
                }
                if ((j & 31) == 0) { candV[j >> 5] = v; candI[j >> 5] = bi; }
            }
            __syncthreads();
            if (tid == 0) {
                float v  = candV[0];
                int   bi = candI[0];
                #pragma unroll
                for (int w = 1; w < 4; w++)
                    if (candV[w] > v || (candV[w] == v && candI[w] < bi)) {
                        v = candV[w]; bi = candI[w];
                    }
                out[(size_t)b * Tlen + t] = (float)bi;   // float32 output
                g_prev[b] = bi;
            }
        }

        grid_sync();   // g_prev(t) visible before phase 1 of t+1
    }
}

// ---------------- launch ----------------
extern "C" void kernel_launch(void* const* d_in, const int* in_sizes, int n_in,
                              void* d_out, int out_size) {
    (void)out_size;
    const float *xc = 0, *xw = 0, *W = 0, *U = 0, *bias = 0, *Ws = 0, *bs = 0;
    for (int i = 0; i < n_in; i++) {
        switch (in_sizes[i]) {
            case 4194304:  xc   = (const float*)d_in[i]; break;
            case 16777216: xw   = (const float*)d_in[i]; break;
            case 1572864:  W    = (const float*)d_in[i]; break;
            case 1048576:  U    = (const float*)d_in[i]; break;
            case 2048:     bias = (const float*)d_in[i]; break;
            case 65536:    Ws   = (const float*)d_in[i]; break;
            case 128:      bs   = (const float*)d_in[i]; break;
            default: break;
        }
    }
    if ((!xc || !xw || !W || !U || !bias || !Ws || !bs) && n_in >= 7) {
        xc = (const float*)d_in[0]; xw = (const float*)d_in[1];
        W  = (const float*)d_in[2]; U  = (const float*)d_in[3];
        bias = (const float*)d_in[4]; Ws = (const float*)d_in[5];
        bs = (const float*)d_in[6];
    }
    float* out = (float*)d_out;

    cudaFuncSetAttribute(k_scan, cudaFuncAttributeMaxDynamicSharedMemorySize, DSMEM);

    k_init<<<256, 256>>>();
    k_packW<<<(KTOT * 2048) / 256, 256>>>(W, U);
    k_packMisc<<<(128 * 2048) / 256, 256>>>(W, bias);
    {
        dim3 g(Tlen, KX / 32, Bsz / 32);
        dim3 b(32, 8);
        k_xT<<<g, b>>>(xc, xw);
    }
    k_scan<<<NBLK, 256, DSMEM>>>(Ws, bs, out);
}

// round 9
// speedup vs baseline: 1.8055x; 1.0619x over previous
#include <cuda_runtime.h>
#include <math.h>
#include <stdint.h>

#define Bsz   128
#define Tlen  256
#define NCLS  128
#define WD    512
#define UNITS 512
#define N4    2048      // 4*UNITS
#define KX    640       // NC + WD
#define KTOT  1152      // KX + UNITS
#define NCH   18        // KTOT / 64
#define NBLK  128       // persistent grid (all co-resident: 1 block/SM, 128 <= 148)

typedef unsigned long long ull;

// ---------------- device scratch ----------------
__device__ float g_h [2][UNITS * Bsz];          // [u][b], double-buffered
__device__ float g_hT[Bsz * UNITS];             // [b][u], phase-2 staging
__device__ float g_c [UNITS * Bsz];             // [u][b]
__device__ int   g_prev[Bsz];                   // prev argmax (-1 => t==0)
__device__ ull   g_Wp[(size_t)128 * KTOT * 16]; // packed (w,w): [block][k][c]
__device__ float g_Wfb[(size_t)NCLS * N4];      // feedback rows, packed col order
__device__ float g_biasP[N4];                   // bias, packed col order
__device__ float g_SP[N4];                      // start-vec colsum, packed order
__device__ float g_xT[(size_t)Tlen * KX * Bsz]; // x transposed: [t][k][b]
__device__ unsigned          g_bar_count;
__device__ volatile unsigned g_bar_gen;

__device__ __forceinline__ void ffma2(ull& d, ull a, ull b) {
    asm("fma.rn.f32x2 %0, %1, %2, %0;" : "+l"(d) : "l"(a), "l"(b));
}
__device__ __forceinline__ void cpa16(uint32_t dst, const void* src) {
    asm volatile("cp.async.cg.shared.global [%0], [%1], 16;" :: "r"(dst), "l"(src) : "memory");
}
__device__ __forceinline__ void cpa_commit() {
    asm volatile("cp.async.commit_group;" ::: "memory");
}

__device__ __forceinline__ void col2bc(int col, int& blk, int& c) {
    int g = col >> 9;
    int u = col & 511;
    blk   = u >> 2;
    c     = (u & 3) * 4 + g;
}

__device__ __forceinline__ void grid_sync() {
    __syncthreads();
    if (threadIdx.x == 0) {
        __threadfence();
        unsigned gen = g_bar_gen;
        if (atomicAdd(&g_bar_count, 1u) == NBLK - 1) {
            g_bar_count = 0;
            __threadfence();
            g_bar_gen = gen + 1;
        } else {
            while (g_bar_gen == gen) __nanosleep(16);
        }
        __threadfence();
    }
    __syncthreads();
}

// ---------------- init ----------------
__global__ void k_init() {
    int i = blockIdx.x * blockDim.x + threadIdx.x;   // 65536
    g_h[0][i] = 0.0f;
    g_c[i]    = 0.0f;
    if (i < Bsz) g_prev[i] = -1;
    if (i == 0) { g_bar_count = 0; g_bar_gen = 0; }
}

// ---------------- one-time packs ----------------
__global__ void k_packW(const float* __restrict__ W, const float* __restrict__ U) {
    int idx = blockIdx.x * blockDim.x + threadIdx.x;
    int k   = idx >> 11;
    int col = idx & 2047;
    if (k >= KTOT) return;
    float w = (k < KX) ? W[(size_t)k * N4 + col] : U[(size_t)(k - KX) * N4 + col];
    int blk, c; col2bc(col, blk, c);
    ull p;
    asm("mov.b64 %0, {%1, %2};" : "=l"(p) : "f"(w), "f"(w));
    g_Wp[((size_t)blk * KTOT + k) * 16 + c] = p;
}

__global__ void k_packMisc(const float* __restrict__ W, const float* __restrict__ bias) {
    int idx = blockIdx.x * blockDim.x + threadIdx.x;
    int pi  = idx >> 11;
    int col = idx & 2047;
    int blk, c; col2bc(col, blk, c);
    int dst = blk * 16 + c;
    g_Wfb[(size_t)pi * N4 + dst] = W[(size_t)(KX + pi) * N4 + col];
    if (pi == 0) {
        g_biasP[dst] = bias[col];
        float s = 0.0f;
        #pragma unroll
        for (int i = 0; i < NCLS; i++) s += W[(size_t)(KX + i) * N4 + col];
        g_SP[dst] = s;
    }
}

__global__ void k_xT(const float* __restrict__ xc, const float* __restrict__ xw) {
    __shared__ float tile[32][33];
    int t  = blockIdx.x;
    int kt = blockIdx.y;
    int bt = blockIdx.z;
    int tx = threadIdx.x;
    int ty = threadIdx.y;
    #pragma unroll
    for (int i = 0; i < 4; i++) {
        int b = bt * 32 + ty + 8 * i;
        int k = kt * 32 + tx;
        float v = (k < NCLS) ? xc[((size_t)b * Tlen + t) * NCLS + k]
                             : xw[((size_t)b * Tlen + t) * WD + (k - NCLS)];
        tile[ty + 8 * i][tx] = v;
    }
    __syncthreads();
    #pragma unroll
    for (int i = 0; i < 4; i++) {
        int k = kt * 32 + ty + 8 * i;
        int b = bt * 32 + tx;
        g_xT[((size_t)t * KX + k) * Bsz + b] = tile[tx][ty + 8 * i];
    }
}

// dummy launch so ncu (-s 5 -c 1) captures k_scan as launch #6
__global__ void k_dummy() {}

// ---------------- persistent scan kernel ----------------
// dynamic smem: [ ws_all: KTOT*16 ull = 147456 B ][ vs: 2*64*132 f32 = 67584 B ]
#define WSALL_B (KTOT * 16 * 8)
#define VS_ELE  (64 * 132)
#define DSMEM   (WSALL_B + 2 * VS_ELE * 4)     // 215040 B

__global__ __launch_bounds__(256) void k_scan(const float* __restrict__ Ws,
                                              const float* __restrict__ bsv,
                                              float* __restrict__ out) {
    extern __shared__ char sm[];
    ull*   ws_all = (ull*)sm;                  // [KTOT][16]
    float* vsb    = (float*)(sm + WSALL_B);    // [2][64][132]
    __shared__ float hs[4][UNITS];             // 8 KB (phase 2)
    __shared__ float candV[2][2][4];
    __shared__ int   candI[2][2][4];

    const int tid = threadIdx.x;
    const int bq  = tid & 63;
    const int cq  = tid >> 6;                  // local unit 0..3 (owns 4 gates)
    const int blk = blockIdx.x;
    const uint32_t vs_s = (uint32_t)__cvta_generic_to_shared(vsb);
    const uint32_t ws_s = (uint32_t)__cvta_generic_to_shared(ws_all);

    // ---- preload this block's full weight slice into smem (once) ----
    {
        const char* src = (const char*)(g_Wp + (size_t)blk * KTOT * 16);
        #pragma unroll
        for (int i = 0; i < 36; i++) {         // 9216 x 16B / 256 thr
            int q = tid + 256 * i;
            cpa16(ws_s + q * 16, src + (size_t)q * 16);
        }
        cpa_commit();
        asm volatile("cp.async.wait_group 0;" ::: "memory");
        __syncthreads();
    }

    for (int t = 0; t < Tlen; t++) {
        const float* __restrict__ hin = g_h[t & 1];
        float* hout = g_h[(t + 1) & 1];

        // -------- phase 1: z = x@W + h@U (K=1152), 16 cols x 128 b --------
        auto issue = [&](int ch, int buf) {
            const float* src = (ch < 10)
                ? g_xT + ((size_t)t * KX + ch * 64) * Bsz
                : hin  + (size_t)(ch - 10) * 64 * Bsz;
            uint32_t vdst = vs_s + WSALL_B - 0;          // (unused guard)
            vdst = vs_s + buf * VS_ELE * 4;
            #pragma unroll
            for (int i = 0; i < 8; i++) {
                int vi = tid + 256 * i;                  // 0..2047 float4s
                int k  = vi >> 5;
                int b4 = vi & 31;
                cpa16(vdst + (k * 132 + b4 * 4) * 4, src + k * Bsz + b4 * 4);
            }
            cpa_commit();
        };

        ull acc[4] = {0ull, 0ull, 0ull, 0ull};
        issue(0, 0);
        issue(1, 1);

        for (int ch = 0; ch < NCH; ch++) {
            if (ch < NCH - 2) asm volatile("cp.async.wait_group 1;" ::: "memory");
            else              asm volatile("cp.async.wait_group 0;" ::: "memory");
            __syncthreads();

            const float* vrow = vsb + (ch & 1) * VS_ELE;
            const ull*   wrow = ws_all + ch * 64 * 16;

            #pragma unroll 8
            for (int k = 0; k < 64; k++) {
                ull hv = *(const ull*)(vrow + k * 132 + 2 * bq);
                const ull* wr = wrow + k * 16 + cq * 4;
                ulonglong2 wA = *(const ulonglong2*)&wr[0];
                ulonglong2 wB = *(const ulonglong2*)&wr[2];
                ffma2(acc[0], hv, wA.x);  ffma2(acc[1], hv, wA.y);
                ffma2(acc[2], hv, wB.x);  ffma2(acc[3], hv, wB.y);
            }
            __syncthreads();
            if (ch + 2 < NCH) issue(ch + 2, ch & 1);
        }

        // epilogue: gates (Keras i,f,g,o) -> new c, h
        const int u    = blk * 4 + cq;
        const int dstb = blk * 16 + cq * 4;
        float zl[4], zh[4];
        #pragma unroll
        for (int g = 0; g < 4; g++)
            asm("mov.b64 {%0, %1}, %2;" : "=f"(zl[g]), "=f"(zh[g]) : "l"(acc[g]));

        #pragma unroll
        for (int r = 0; r < 2; r++) {
            const int b  = 2 * bq + r;
            const int pi = g_prev[b];
            float z[4];
            #pragma unroll
            for (int g = 0; g < 4; g++) {
                float add = (pi < 0) ? 1e-5f * g_SP[dstb + g]
                                     : __ldg(&g_Wfb[(size_t)pi * N4 + dstb + g]);
                z[g] = (r ? zh[g] : zl[g]) + g_biasP[dstb + g] + add;
            }
            float i_ = 1.0f / (1.0f + expf(-z[0]));
            float f_ = 1.0f / (1.0f + expf(-z[1]));
            float gv = tanhf(z[2]);
            float o_ = 1.0f / (1.0f + expf(-z[3]));
            float cn = f_ * g_c[(size_t)u * Bsz + b] + i_ * gv;
            float hn = o_ * tanhf(cn);
            g_c[(size_t)u * Bsz + b]    = cn;
            hout[(size_t)u * Bsz + b]   = hn;
            g_hT[(size_t)b * UNITS + u] = hn;
        }

        grid_sync();   // h(t+1) complete everywhere

        // -------- phase 2: blocks 0..31 compute logits+argmax for 4 batches ------
        if (blk < 32) {
            const int b0 = blk * 4;
            const int j  = tid & 127;
            const int rr = tid >> 7;           // 0..1 -> batches (b0+2rr, b0+2rr+1)

            // stage h for 4 batches (coalesced float4)
            #pragma unroll
            for (int i = 0; i < 2; i++) {
                int idx = tid + 256 * i;       // 0..511 float4s
                int r   = idx >> 7;
                int off = (idx & 127) * 4;
                *(float4*)&hs[r][off] = *(const float4*)&g_hT[(size_t)(b0 + r) * UNITS + off];
            }
            __syncthreads();

            // stream Ws through smem (reuse vs area): 16 chunks of [32k x 128j] = 16 KB
            auto issueW = [&](int c, int buf) {
                const float* src = Ws + (size_t)c * 32 * NCLS;
                uint32_t dst = vs_s + buf * 16384;
                #pragma unroll
                for (int q = 0; q < 4; q++) {
                    int e = tid + 256 * q;     // 0..1023 x 16B
                    cpa16(dst + e * 16, src + e * 4);
                }
                cpa_commit();
            };

            float a0 = 0.0f, a1 = 0.0f;
            issueW(0, 0);
            issueW(1, 1);
            for (int c = 0; c < 16; c++) {
                if (c < 14) asm volatile("cp.async.wait_group 1;" ::: "memory");
                else        asm volatile("cp.async.wait_group 0;" ::: "memory");
                __syncthreads();
                const float* wch = vsb + (c & 1) * 4096;
                const int base = c * 32;
                #pragma unroll
                for (int k = 0; k < 32; k++) {
                    float w = wch[k * NCLS + j];
                    a0 += hs[2 * rr + 0][base + k] * w;
                    a1 += hs[2 * rr + 1][base + k] * w;
                }
                __syncthreads();
                if (c + 2 < 16) issueW(c + 2, c & 1);
            }
            float bj = __ldg(&bsv[j]);
            a0 += bj;  a1 += bj;

            // argmax (tie -> lowest index) per batch
            const int wj = j >> 5;
            #pragma unroll
            for (int r = 0; r < 2; r++) {
                float v  = r ? a1 : a0;
                int   bi = j;
                #pragma unroll
                for (int off = 16; off > 0; off >>= 1) {
                    float ov = __shfl_down_sync(0xffffffffu, v, off);
                    int   oi = __shfl_down_sync(0xffffffffu, bi, off);
                    if (ov > v || (ov == v && oi < bi)) { v = ov; bi = oi; }
                }
                if ((j & 31) == 0) { candV[rr][r][wj] = v; candI[rr][r][wj] = bi; }
            }
            __syncthreads();
            if (j == 0) {
                #pragma unroll
                for (int r = 0; r < 2; r++) {
                    float v  = candV[rr][r][0];
                    int   bi = candI[rr][r][0];
                    #pragma unroll
                    for (int w = 1; w < 4; w++)
                        if (candV[rr][r][w] > v ||
                            (candV[rr][r][w] == v && candI[rr][r][w] < bi)) {
                            v = candV[rr][r][w]; bi = candI[rr][r][w];
                        }
                    const int b = b0 + 2 * rr + r;
                    out[(size_t)b * Tlen + t] = (float)bi;   // float32 output
                    g_prev[b] = bi;
                }
            }
        }

        grid_sync();   // g_prev(t) visible before phase 1 of t+1
    }
}

// ---------------- launch ----------------
extern "C" void kernel_launch(void* const* d_in, const int* in_sizes, int n_in,
                              void* d_out, int out_size) {
    (void)out_size;
    const float *xc = 0, *xw = 0, *W = 0, *U = 0, *bias = 0, *Ws = 0, *bs = 0;
    for (int i = 0; i < n_in; i++) {
        switch (in_sizes[i]) {
            case 4194304:  xc   = (const float*)d_in[i]; break;
            case 16777216: xw   = (const float*)d_in[i]; break;
            case 1572864:  W    = (const float*)d_in[i]; break;
            case 1048576:  U    = (const float*)d_in[i]; break;
            case 2048:     bias = (const float*)d_in[i]; break;
            case 65536:    Ws   = (const float*)d_in[i]; break;
            case 128:      bs   = (const float*)d_in[i]; break;
            default: break;
        }
    }
    if ((!xc || !xw || !W || !U || !bias || !Ws || !bs) && n_in >= 7) {
        xc = (const float*)d_in[0]; xw = (const float*)d_in[1];
        W  = (const float*)d_in[2]; U  = (const float*)d_in[3];
        bias = (const float*)d_in[4]; Ws = (const float*)d_in[5];
        bs = (const float*)d_in[6];
    }
    float* out = (float*)d_out;

    cudaFuncSetAttribute(k_scan, cudaFuncAttributeMaxDynamicSharedMemorySize, DSMEM);

    k_init<<<256, 256>>>();                                   // launch 1
    k_packW<<<(KTOT * 2048) / 256, 256>>>(W, U);              // launch 2
    k_packMisc<<<(128 * 2048) / 256, 256>>>(W, bias);         // launch 3
    {
        dim3 g(Tlen, KX / 32, Bsz / 32);
        dim3 b(32, 8);
        k_xT<<<g, b>>>(xc, xw);                               // launch 4
    }
    k_dummy<<<1, 32>>>();                                     // launch 5 (ncu skip target)
    k_scan<<<NBLK, 256, DSMEM>>>(Ws, bs, out);                // launch 6 (ncu captures)
}